// round 4
// baseline (speedup 1.0000x reference)
#include <cuda_runtime.h>
#include <cstdint>

#define NPTS 8192
#define NB   4
#define NC   64
#define NK   16
#define BNSCALE 0.9999950000374997f

typedef unsigned long long u64;

union F2 { u64 u; float2 f; };
union U4 { uint4 v; u64 u[2]; };

__device__ __forceinline__ void fma2(u64 &d, u64 a, u64 b) {
    asm("fma.rn.f32x2 %0,%1,%2,%0;" : "+l"(d) : "l"(a), "l"(b));
}
__device__ __forceinline__ u64 fma2i(u64 a, u64 b, u64 c) {
    u64 d; asm("fma.rn.f32x2 %0,%1,%2,%3;" : "=l"(d) : "l"(a), "l"(b), "l"(c)); return d;
}
__device__ __forceinline__ u64 pk2(float x, float y) { F2 t; t.f.x = x; t.f.y = y; return t.u; }
__device__ __forceinline__ u64 relu2(u64 a) {
    F2 t; t.u = a; t.f.x = fmaxf(t.f.x, 0.f); t.f.y = fmaxf(t.f.y, 0.f); return t.u;
}

// ---------------- device scratch ----------------
__device__ __align__(16) float dZ[NB * NPTS * NC];   // z[b][n][c], contiguous rows
__device__ float dX1[NB * NC * NPTS];                // x after block 0
// scalar fused params
__device__ float dW1f[2][NC * 3];
__device__ float dC0 [2][NC];
__device__ __align__(16) float dM  [2][NC * NC];     // row-major
__device__ float dC1 [2][NC];
__device__ float dA1T[2][NC * NC];
__device__ __align__(16) float dA2 [2][NC * NC];
__device__ __align__(16) float dD  [2][NC * NC];
__device__ float dC2 [2][NC];
__device__ float dCd [2][NC];
// packed params
__device__ __align__(16) u64 dW1xp[2][32];
__device__ __align__(16) u64 dW1yp[2][32];
__device__ __align__(16) u64 dW1zp[2][32];
__device__ __align__(16) u64 dC0p [2][32];
__device__ __align__(16) u64 dA2cp[2][NC * 32];      // [c][rowpair]
__device__ __align__(16) u64 dDcp [2][NC * 32];      // [c][rowpair]

// ---------------- prep: fold BN affines, fuse, pack ---------------------
__global__ void prep_kernel(
    const float* __restrict__ dw1, const float* __restrict__ db1,
    const float* __restrict__ dg1, const float* __restrict__ dbe1,
    const float* __restrict__ dw2, const float* __restrict__ db2,
    const float* __restrict__ dg2, const float* __restrict__ dbe2,
    const float* __restrict__ aw1, const float* __restrict__ ab1,
    const float* __restrict__ ag1, const float* __restrict__ abe1,
    const float* __restrict__ aw2, const float* __restrict__ ab2,
    const float* __restrict__ ag2, const float* __restrict__ abe2,
    const float* __restrict__ lw,  const float* __restrict__ lb,
    const float* __restrict__ lg,  const float* __restrict__ lbe)
{
    int L = blockIdx.x;
    int o = threadIdx.x;
    int vo = L * NC + o;
    float S1  = dg1[vo] * BNSCALE;
    float Sa1 = ag1[vo] * BNSCALE;
    float Sa2 = ag2[vo] * BNSCALE;
    float Sd  = lg [vo] * BNSCALE;

    #pragma unroll
    for (int j = 0; j < 3; j++) dW1f[L][o * 3 + j] = S1 * dw1[vo * 3 + j];
    dC0[L][o] = fmaf(S1, db1[vo], dbe1[vo]);

    float Mrow[NC];
    #pragma unroll
    for (int c = 0; c < NC; c++) Mrow[c] = 0.f;
    float t2dot = 0.f;
    for (int m = 0; m < NC; m++) {
        int vm = L * NC + m;
        float S2m = dg2[vm] * BNSCALE;
        float w   = aw1[vo * NC + m];
        t2dot = fmaf(w, fmaf(S2m, db2[vm], dbe2[vm]), t2dot);
        float ws = w * S2m;
        #pragma unroll
        for (int c = 0; c < NC; c++) Mrow[c] = fmaf(ws, dw2[vm * NC + c], Mrow[c]);
        dA1T[L][m * NC + o] = Sa1 * w;
    }
    #pragma unroll
    for (int c = 0; c < NC; c++) dM[L][o * NC + c] = Sa1 * Mrow[c];
    dC1[L][o] = fmaf(Sa1, t2dot + ab1[vo], abe1[vo]);

    #pragma unroll
    for (int c = 0; c < NC; c++) dA2[L][o * NC + c] = Sa2 * aw2[vo * NC + c];
    dC2[L][o] = fmaf(Sa2, ab2[vo], abe2[vo]);
    #pragma unroll
    for (int c = 0; c < NC; c++) dD[L][o * NC + c] = Sd * lw[vo * NC + c];
    dCd[L][o] = fmaf(Sd, lb[vo], lbe[vo]);

    __syncthreads();   // block covers whole layer L; global writes visible in-block

    if (o < 32) {
        dW1xp[L][o] = pk2(dW1f[L][(2*o)*3 + 0], dW1f[L][(2*o+1)*3 + 0]);
        dW1yp[L][o] = pk2(dW1f[L][(2*o)*3 + 1], dW1f[L][(2*o+1)*3 + 1]);
        dW1zp[L][o] = pk2(dW1f[L][(2*o)*3 + 2], dW1f[L][(2*o+1)*3 + 2]);
        dC0p [L][o] = pk2(dC0[L][2*o], dC0[L][2*o+1]);
    }
    // column-major pair-packed A2 / D: thread o = column c
    for (int r2 = 0; r2 < 32; r2++) {
        dA2cp[L][o * 32 + r2] = pk2(dA2[L][(2*r2) * NC + o], dA2[L][(2*r2+1) * NC + o]);
        dDcp [L][o * 32 + r2] = pk2(dD [L][(2*r2) * NC + o], dD [L][(2*r2+1) * NC + o]);
    }
}

// ---------------- z = A1f @ x  -----------------------------------------
__global__ void z_kernel(const float* __restrict__ x_param, int layer)
{
    __shared__ float As[NC * NC];
    __shared__ float xs[NC * NC];
    const float* x = layer ? dX1 : x_param;
    int tid = threadIdx.x;
    int b = blockIdx.y;
    int n0 = blockIdx.x * 64;

    for (int i = tid; i < NC * NC; i += 256) As[i] = dA1T[layer][i];
    for (int i = tid; i < NC * NC; i += 256) {
        int m = i >> 6, nl = i & 63;
        xs[i] = x[((size_t)(b * NC + m)) * NPTS + n0 + nl];
    }
    __syncthreads();

    int c  = tid & 63;
    int nb = tid >> 6;
    for (int nl = nb; nl < 64; nl += 4) {
        float acc = 0.f;
        #pragma unroll
        for (int m = 0; m < NC; m++) acc = fmaf(As[m * 64 + c], xs[m * 64 + nl], acc);
        dZ[(((size_t)b * NPTS) + n0 + nl) * 64 + c] = acc;
    }
}

// ---------------- main fused kernel: 2 threads/point, f32x2 -------------
__global__ void __launch_bounds__(128, 2) main_kernel(
    const float* __restrict__ p, const float* __restrict__ x_param,
    const int* __restrict__ idx, float* __restrict__ out_param, int layer)
{
    __shared__ float Ms[NC * NC];          // row-major
    __shared__ u64   A2s[NC * 32];         // [c][rowpair]
    __shared__ u64   wxs[32], wys[32], wzs[32], c0s[32];
    __shared__ float c1s[NC], c2s[NC], cds[NC];

    int tid = threadIdx.x;
    for (int i = tid; i < NC * NC; i += 128) Ms[i] = dM[layer][i];
    for (int i = tid; i < NC * 32; i += 128) A2s[i] = dA2cp[layer][i];
    if (tid < 32) {
        wxs[tid] = dW1xp[layer][tid]; wys[tid] = dW1yp[layer][tid];
        wzs[tid] = dW1zp[layer][tid]; c0s[tid] = dC0p[layer][tid];
    }
    if (tid < NC) {
        c1s[tid] = dC1[layer][tid]; c2s[tid] = dC2[layer][tid]; cds[tid] = dCd[layer][tid];
    }
    __syncthreads();

    int hf = tid & 1;
    int rb = hf * 32;
    int g  = blockIdx.x * 64 + (tid >> 1);
    int b  = g >> 13;
    int n  = g & (NPTS - 1);

    const float* pb = p + (size_t)b * 3 * NPTS;
    float pnx = pb[n], pny = pb[NPTS + n], pnz = pb[2 * NPTS + n];
    const int* ip = idx + ((size_t)(b * NPTS) + n) * NK;
    const float* zb = dZ + (size_t)b * NPTS * NC;

    const float* x_in  = layer ? dX1 : x_param;
    float*       x_out = layer ? out_param : dX1;

    const uint4* wx4 = (const uint4*)wxs;
    const uint4* wy4 = (const uint4*)wys;
    const uint4* wz4 = (const uint4*)wzs;
    const uint4* c04 = (const uint4*)c0s;
    const uint4* M4  = (const uint4*)Ms;
    const uint4* A4  = (const uint4*)(A2s + rb * 32);   // own 32 columns

    float y[32];
    #pragma unroll
    for (int i = 0; i < 32; i++) y[i] = 0.f;

    // software pipeline for idx + p gathers
    const uint4* ipv = (const uint4*)ip;
    uint4 jq = ipv[0];
    int jn = jq.x;
    float qxn = pb[jn], qyn = pb[NPTS + jn], qzn = pb[2 * NPTS + jn];

    #pragma unroll 1
    for (int k = 0; k < NK; k++) {
        int j = jn;
        float qx = qxn, qy = qyn, qz = qzn;

        // prefetch z row (own half, 8 float4)
        float4 zv[8];
        const float4* zr = (const float4*)(zb + (size_t)j * NC) + hf * 8;
        #pragma unroll
        for (int og = 0; og < 8; og++) zv[og] = zr[og];

        // prefetch next neighbor's index + coords
        if (k < NK - 1) {
            int km = (k + 1) & 3;
            if (km == 0) jq = ipv[(k + 1) >> 2];
            jn = (km == 0) ? jq.x : (km == 1) ? jq.y : (km == 2) ? jq.z : jq.w;
            qxn = pb[jn]; qyn = pb[NPTS + jn]; qzn = pb[2 * NPTS + jn];
        }

        u64 rxx = pk2(pnx - qx, pnx - qx);
        u64 ryy = pk2(pny - qy, pny - qy);
        u64 rzz = pk2(pnz - qz, pnz - qz);

        // ---- h = relu(W1f @ rel + c0): ALL 32 pairs (16 uint4 groups) ----
        u64 h2[32];
        #pragma unroll
        for (int i2 = 0; i2 < 16; i2++) {
            U4 ax; ax.v = wx4[i2];
            U4 ay; ay.v = wy4[i2];
            U4 az; az.v = wz4[i2];
            U4 ac; ac.v = c04[i2];
            u64 t0 = fma2i(az.u[0], rzz, ac.u[0]);
            t0 = fma2i(ay.u[0], ryy, t0);
            t0 = fma2i(ax.u[0], rxx, t0);
            h2[2*i2]   = relu2(t0);
            u64 t1 = fma2i(az.u[1], rzz, ac.u[1]);
            t1 = fma2i(ay.u[1], ryy, t1);
            t1 = fma2i(ax.u[1], rxx, t1);
            h2[2*i2+1] = relu2(t1);
        }

        // ---- v[own 32] = relu(M[own rows] @ h + z + c1) ----
        float v[32];
        #pragma unroll
        for (int og = 0; og < 8; og++) {
            int r0 = rb + og * 4;
            u64 a0 = 0, a1 = 0, a2 = 0, a3 = 0;
            #pragma unroll
            for (int cg = 0; cg < 16; cg++) {
                U4 m0; m0.v = M4[(r0 + 0) * 16 + cg];
                U4 m1; m1.v = M4[(r0 + 1) * 16 + cg];
                U4 m2; m2.v = M4[(r0 + 2) * 16 + cg];
                U4 m3; m3.v = M4[(r0 + 3) * 16 + cg];
                u64 hA = h2[2*cg], hB = h2[2*cg + 1];
                fma2(a0, m0.u[0], hA); fma2(a0, m0.u[1], hB);
                fma2(a1, m1.u[0], hA); fma2(a1, m1.u[1], hB);
                fma2(a2, m2.u[0], hA); fma2(a2, m2.u[1], hB);
                fma2(a3, m3.u[0], hA); fma2(a3, m3.u[1], hB);
            }
            float4 z4 = zv[og];
            F2 t;
            t.u = a0; v[og*4+0] = fmaxf(t.f.x + t.f.y + z4.x + c1s[r0+0], 0.f);
            t.u = a1; v[og*4+1] = fmaxf(t.f.x + t.f.y + z4.y + c1s[r0+1], 0.f);
            t.u = a2; v[og*4+2] = fmaxf(t.f.x + t.f.y + z4.z + c1s[r0+2], 0.f);
            t.u = a3; v[og*4+3] = fmaxf(t.f.x + t.f.y + z4.w + c1s[r0+3], 0.f);
        }

        // ---- a = relu(A2 @ v + c2); y = max(y, a). Column rank-1 form ----
        {
            u64 acc[32];
            #pragma unroll
            for (int q = 0; q < 32; q++) acc[q] = 0;
            #pragma unroll
            for (int c = 0; c < 32; c++) {
                u64 vv = pk2(v[c], v[c]);
                #pragma unroll
                for (int q8 = 0; q8 < 16; q8++) {
                    U4 m; m.v = A4[c * 16 + q8];
                    fma2(acc[2*q8],   m.u[0], vv);
                    fma2(acc[2*q8+1], m.u[1], vv);
                }
            }
            int ob = rb >> 1;
            int qb = ob ^ 16;
            #pragma unroll
            for (int q = 0; q < 16; q++) {
                F2 po; po.u = acc[qb + q];
                float plo = __shfl_xor_sync(0xffffffffu, po.f.x, 1);
                float phi = __shfl_xor_sync(0xffffffffu, po.f.y, 1);
                F2 ow; ow.u = acc[ob + q];
                float r0v = ow.f.x + plo + c2s[rb + 2*q];
                float r1v = ow.f.y + phi + c2s[rb + 2*q + 1];
                y[2*q]   = fmaxf(y[2*q],   fmaxf(r0v, 0.f));
                y[2*q+1] = fmaxf(y[2*q+1], fmaxf(r1v, 0.f));
            }
        }
    }

    // ---- out = D @ y + cd + x_in (column rank-1, D via __ldg) ----
    {
        const uint4* D4 = (const uint4*)(dDcp[layer] + rb * 32);
        u64 acc[32];
        #pragma unroll
        for (int q = 0; q < 32; q++) acc[q] = 0;
        #pragma unroll
        for (int c = 0; c < 32; c++) {
            u64 yy = pk2(y[c], y[c]);
            #pragma unroll
            for (int q8 = 0; q8 < 16; q8++) {
                U4 m; m.v = __ldg(&D4[c * 16 + q8]);
                fma2(acc[2*q8],   m.u[0], yy);
                fma2(acc[2*q8+1], m.u[1], yy);
            }
        }
        float*       xo = x_out + ((size_t)b * NC) * NPTS + n;
        const float* xi = x_in  + ((size_t)b * NC) * NPTS + n;
        int ob = rb >> 1;
        int qb = ob ^ 16;
        #pragma unroll
        for (int q = 0; q < 16; q++) {
            F2 po; po.u = acc[qb + q];
            float plo = __shfl_xor_sync(0xffffffffu, po.f.x, 1);
            float phi = __shfl_xor_sync(0xffffffffu, po.f.y, 1);
            F2 ow; ow.u = acc[ob + q];
            int r = rb + 2*q;
            xo[(size_t)r * NPTS]       = ow.f.x + plo + cds[r]     + xi[(size_t)r * NPTS];
            xo[(size_t)(r+1) * NPTS]   = ow.f.y + phi + cds[r + 1] + xi[(size_t)(r+1) * NPTS];
        }
    }
}

// ---------------- launch ------------------------------------------------
extern "C" void kernel_launch(void* const* d_in, const int* in_sizes, int n_in,
                              void* d_out, int out_size)
{
    const float* p   = (const float*)d_in[0];
    const float* x   = (const float*)d_in[1];
    const int*   idx = (const int*)d_in[2];

    prep_kernel<<<2, 64>>>(
        (const float*)d_in[3],  (const float*)d_in[4],  (const float*)d_in[5],  (const float*)d_in[6],
        (const float*)d_in[7],  (const float*)d_in[8],  (const float*)d_in[9],  (const float*)d_in[10],
        (const float*)d_in[11], (const float*)d_in[12], (const float*)d_in[13], (const float*)d_in[14],
        (const float*)d_in[15], (const float*)d_in[16], (const float*)d_in[17], (const float*)d_in[18],
        (const float*)d_in[19], (const float*)d_in[20], (const float*)d_in[21], (const float*)d_in[22]);

    float* out_p = (float*)d_out;
    float* out_x = (float*)d_out + NB * 3 * NPTS;

    cudaMemcpyAsync(out_p, p, (size_t)NB * 3 * NPTS * sizeof(float),
                    cudaMemcpyDeviceToDevice);

    dim3 zgrid(NPTS / 64, NB);
    z_kernel<<<zgrid, 256>>>(x, 0);
    main_kernel<<<(NB * NPTS + 63) / 64, 128>>>(p, x, idx, out_x, 0);
    z_kernel<<<zgrid, 256>>>(x, 1);
    main_kernel<<<(NB * NPTS + 63) / 64, 128>>>(p, x, idx, out_x, 1);
}

// round 5
// speedup vs baseline: 2.2401x; 2.2401x over previous
#include <cuda_runtime.h>
#include <cstdint>

#define NPTS 8192
#define NB   4
#define NC   64
#define NK   16
#define TPB  8          // points per block (main kernel)
#define BNSCALE 0.9999950000374997f

typedef unsigned long long u64;

union F2 { u64 u; float2 f; };
union U4 { uint4 v; u64 u[2]; };

__device__ __forceinline__ void fma2(u64 &d, u64 a, u64 b) {
    asm("fma.rn.f32x2 %0,%1,%2,%0;" : "+l"(d) : "l"(a), "l"(b));
}
__device__ __forceinline__ u64 fma2i(u64 a, u64 b, u64 c) {
    u64 d; asm("fma.rn.f32x2 %0,%1,%2,%3;" : "=l"(d) : "l"(a), "l"(b), "l"(c)); return d;
}
__device__ __forceinline__ u64 pk2(float x, float y) { F2 t; t.f.x = x; t.f.y = y; return t.u; }
__device__ __forceinline__ u64 dup2(float x) {
    u64 d; unsigned r = __float_as_uint(x);
    asm("mov.b64 %0,{%1,%1};" : "=l"(d) : "r"(r)); return d;
}
__device__ __forceinline__ u64 relu2(u64 a) {
    F2 t; t.u = a; t.f.x = fmaxf(t.f.x, 0.f); t.f.y = fmaxf(t.f.y, 0.f); return t.u;
}

// ---------------- device scratch ----------------
__device__ __align__(16) float dZ[NB * NPTS * NC];   // z[b][n][c]
__device__ float dX1[NB * NC * NPTS];                // x after block 0
// scalar fused params
__device__ float dW1f[2][NC * 3];
__device__ float dC0 [2][NC];
__device__ __align__(16) float dM  [2][NC * NC];
__device__ float dC1 [2][NC];
__device__ float dA1T[2][NC * NC];
__device__ __align__(16) float dA2 [2][NC * NC];
__device__ __align__(16) float dD  [2][NC * NC];
__device__ float dC2 [2][NC];
__device__ float dCd [2][NC];
// packed params
__device__ __align__(16) u64 dW1xp[2][32];
__device__ __align__(16) u64 dW1yp[2][32];
__device__ __align__(16) u64 dW1zp[2][32];
__device__ __align__(16) u64 dC0p [2][32];
__device__ __align__(16) u64 dMcp [2][NC * 32];      // [c][rowpair]
__device__ __align__(16) u64 dA2cp[2][NC * 32];      // [c][rowpair]
__device__ __align__(16) u64 dDcp [2][NC * 32];      // [c][rowpair]

// ---------------- prep ----------------
__global__ void prep_kernel(
    const float* __restrict__ dw1, const float* __restrict__ db1,
    const float* __restrict__ dg1, const float* __restrict__ dbe1,
    const float* __restrict__ dw2, const float* __restrict__ db2,
    const float* __restrict__ dg2, const float* __restrict__ dbe2,
    const float* __restrict__ aw1, const float* __restrict__ ab1,
    const float* __restrict__ ag1, const float* __restrict__ abe1,
    const float* __restrict__ aw2, const float* __restrict__ ab2,
    const float* __restrict__ ag2, const float* __restrict__ abe2,
    const float* __restrict__ lw,  const float* __restrict__ lb,
    const float* __restrict__ lg,  const float* __restrict__ lbe)
{
    int L = blockIdx.x;
    int o = threadIdx.x;
    int vo = L * NC + o;
    float S1  = dg1[vo] * BNSCALE;
    float Sa1 = ag1[vo] * BNSCALE;
    float Sa2 = ag2[vo] * BNSCALE;
    float Sd  = lg [vo] * BNSCALE;

    #pragma unroll
    for (int j = 0; j < 3; j++) dW1f[L][o * 3 + j] = S1 * dw1[vo * 3 + j];
    dC0[L][o] = fmaf(S1, db1[vo], dbe1[vo]);

    float Mrow[NC];
    #pragma unroll
    for (int c = 0; c < NC; c++) Mrow[c] = 0.f;
    float t2dot = 0.f;
    for (int m = 0; m < NC; m++) {
        int vm = L * NC + m;
        float S2m = dg2[vm] * BNSCALE;
        float w   = aw1[vo * NC + m];
        t2dot = fmaf(w, fmaf(S2m, db2[vm], dbe2[vm]), t2dot);
        float ws = w * S2m;
        #pragma unroll
        for (int c = 0; c < NC; c++) Mrow[c] = fmaf(ws, dw2[vm * NC + c], Mrow[c]);
        dA1T[L][m * NC + o] = Sa1 * w;
    }
    #pragma unroll
    for (int c = 0; c < NC; c++) dM[L][o * NC + c] = Sa1 * Mrow[c];
    dC1[L][o] = fmaf(Sa1, t2dot + ab1[vo], abe1[vo]);

    #pragma unroll
    for (int c = 0; c < NC; c++) dA2[L][o * NC + c] = Sa2 * aw2[vo * NC + c];
    dC2[L][o] = fmaf(Sa2, ab2[vo], abe2[vo]);
    #pragma unroll
    for (int c = 0; c < NC; c++) dD[L][o * NC + c] = Sd * lw[vo * NC + c];
    dCd[L][o] = fmaf(Sd, lb[vo], lbe[vo]);

    __syncthreads();

    if (o < 32) {
        dW1xp[L][o] = pk2(dW1f[L][(2*o)*3 + 0], dW1f[L][(2*o+1)*3 + 0]);
        dW1yp[L][o] = pk2(dW1f[L][(2*o)*3 + 1], dW1f[L][(2*o+1)*3 + 1]);
        dW1zp[L][o] = pk2(dW1f[L][(2*o)*3 + 2], dW1f[L][(2*o+1)*3 + 2]);
        dC0p [L][o] = pk2(dC0[L][2*o], dC0[L][2*o+1]);
    }
    // column-major pair-packed: thread o = column index
    for (int r2 = 0; r2 < 32; r2++) {
        dMcp [L][o * 32 + r2] = pk2(dM [L][(2*r2) * NC + o], dM [L][(2*r2+1) * NC + o]);
        dA2cp[L][o * 32 + r2] = pk2(dA2[L][(2*r2) * NC + o], dA2[L][(2*r2+1) * NC + o]);
        dDcp [L][o * 32 + r2] = pk2(dD [L][(2*r2) * NC + o], dD [L][(2*r2+1) * NC + o]);
    }
}

// ---------------- z = A1f @ x ----------------
__global__ void z_kernel(const float* __restrict__ x_param, int layer)
{
    __shared__ float As[NC * NC];
    __shared__ float xs[NC * NC];
    const float* x = layer ? dX1 : x_param;
    int tid = threadIdx.x;
    int b = blockIdx.y;
    int n0 = blockIdx.x * 64;

    for (int i = tid; i < NC * NC; i += 256) As[i] = dA1T[layer][i];
    for (int i = tid; i < NC * NC; i += 256) {
        int m = i >> 6, nl = i & 63;
        xs[i] = x[((size_t)(b * NC + m)) * NPTS + n0 + nl];
    }
    __syncthreads();

    int c  = tid & 63;
    int nb = tid >> 6;
    for (int nl = nb; nl < 64; nl += 4) {
        float acc = 0.f;
        #pragma unroll
        for (int m = 0; m < NC; m++) acc = fmaf(As[m * 64 + c], xs[m * 64 + nl], acc);
        dZ[(((size_t)b * NPTS) + n0 + nl) * 64 + c] = acc;
    }
}

// ---------------- main: block-level batched GEMM, 8 points/block --------
// smem layout (bytes):
//   0      Hs   float[64*128]   (H, then V)        32768
//   32768  Mp   u64  [64*32]                       16384   (overlaid by ys/y2 after stage2)
//   49152  A2p  u64  [64*32]                       16384
//   65536  wp   u64  [128]  (wx,wy,wz,c0p)          1024
//   66560  c1s  float[64]                            256
//   66816  c2s  float[64]                            256
//   67072  idxs int  [128]                           512
//   67584  pns  float[24]                             96
#define SMEM_BYTES 67712

__global__ void __launch_bounds__(256) main_kernel(
    const float* __restrict__ p, const float* __restrict__ x_param,
    const int* __restrict__ g_idx, float* __restrict__ out_param, int layer)
{
    extern __shared__ char smx[];
    float* Hs   = (float*)smx;
    u64*   Mp   = (u64*)(smx + 32768);
    float* ys   = (float*)(smx + 32768);          // overlay (after stage 2)
    float* yr   = (float*)(smx + 32768 + 8192);   // reduced y [r][t]
    u64*   A2p  = (u64*)(smx + 49152);
    u64*   wp   = (u64*)(smx + 65536);
    float* c1s  = (float*)(smx + 66560);
    float* c2s  = (float*)(smx + 66816);
    int*   idxs = (int*)(smx + 67072);
    float* pns  = (float*)(smx + 67584);

    int tid = threadIdx.x;
    int blk = blockIdx.x;
    int b   = blk >> 10;
    int n0  = (blk & 1023) * TPB;

    const float* pb = p + (size_t)b * 3 * NPTS;
    const float* x_in  = layer ? dX1 : x_param;
    float*       x_out = layer ? out_param : dX1;

    // ---- cooperative loads ----
    for (int i = tid; i < NC * 32; i += 256) { Mp[i] = dMcp[layer][i]; A2p[i] = dA2cp[layer][i]; }
    if (tid < 32) {
        wp[tid]      = dW1xp[layer][tid];
        wp[32 + tid] = dW1yp[layer][tid];
        wp[64 + tid] = dW1zp[layer][tid];
        wp[96 + tid] = dC0p [layer][tid];
    }
    if (tid < NC) { c1s[tid] = dC1[layer][tid]; c2s[tid] = dC2[layer][tid]; }
    if (tid < 128) idxs[tid] = g_idx[((size_t)b * NPTS + n0) * NK + tid];
    if (tid < TPB) {
        pns[tid]      = pb[n0 + tid];
        pns[8 + tid]  = pb[NPTS + n0 + tid];
        pns[16 + tid] = pb[2 * NPTS + n0 + tid];
    }
    __syncthreads();

    int rg = tid >> 5;            // 0..7  (row group: rows rg*8 .. rg*8+7)
    int cg = tid & 31;            // 0..31 (col group: cols cg*4 .. cg*4+3)
    int col0 = cg * 4;

    // ---- z prefetch for stage-2 epilogue (issued a full stage early) ----
    float4 zv0[4], zv1[4];
    {
        const float* zbase = dZ + (size_t)b * NPTS * NC;
        #pragma unroll
        for (int q = 0; q < 4; q++) {
            int j = idxs[col0 + q];
            const float4* zr = (const float4*)(zbase + (size_t)j * NC + rg * 8);
            zv0[q] = zr[0]; zv1[q] = zr[1];
        }
    }

    // ---- stage 1: H = relu(W1f @ rel + c0)  (64 x 128 into smem) ----
    {
        int hf = tid >> 7;          // channel half
        int pr = tid & 127;         // column = t*16+k
        int t  = pr >> 4;
        int j  = idxs[pr];
        u64 rxx = dup2(pns[t]      - pb[j]);
        u64 ryy = dup2(pns[8 + t]  - pb[NPTS + j]);
        u64 rzz = dup2(pns[16 + t] - pb[2 * NPTS + j]);
        const uint4* wx4 = (const uint4*)wp;
        const uint4* wy4 = (const uint4*)(wp + 32);
        const uint4* wz4 = (const uint4*)(wp + 64);
        const uint4* c04 = (const uint4*)(wp + 96);
        float* Hc = Hs + (hf * 32) * 128 + pr;
        #pragma unroll
        for (int i2 = 0; i2 < 8; i2++) {
            U4 ax; ax.v = wx4[hf * 8 + i2];
            U4 ay; ay.v = wy4[hf * 8 + i2];
            U4 az; az.v = wz4[hf * 8 + i2];
            U4 ac; ac.v = c04[hf * 8 + i2];
            u64 t0 = fma2i(ax.u[0], rxx, fma2i(ay.u[0], ryy, fma2i(az.u[0], rzz, ac.u[0])));
            u64 t1 = fma2i(ax.u[1], rxx, fma2i(ay.u[1], ryy, fma2i(az.u[1], rzz, ac.u[1])));
            F2 f0; f0.u = relu2(t0);
            F2 f1; f1.u = relu2(t1);
            Hc[(i2 * 4 + 0) * 128] = f0.f.x;
            Hc[(i2 * 4 + 1) * 128] = f0.f.y;
            Hc[(i2 * 4 + 2) * 128] = f1.f.x;
            Hc[(i2 * 4 + 3) * 128] = f1.f.y;
        }
    }
    __syncthreads();

    // ---- stage 2: V = relu(M @ H + z + c1) ----
    u64 acc[4][4];
    #pragma unroll
    for (int rp = 0; rp < 4; rp++)
        #pragma unroll
        for (int q = 0; q < 4; q++) acc[rp][q] = 0;

    #pragma unroll 8
    for (int c = 0; c < NC; c++) {
        const uint4* mrow = (const uint4*)(Mp + c * 32 + rg * 4);
        U4 m0; m0.v = mrow[0];
        U4 m1; m1.v = mrow[1];
        float4 hv = *(const float4*)(Hs + c * 128 + col0);
        u64 h0 = dup2(hv.x), h1 = dup2(hv.y), h2 = dup2(hv.z), h3 = dup2(hv.w);
        fma2(acc[0][0], m0.u[0], h0); fma2(acc[0][1], m0.u[0], h1);
        fma2(acc[0][2], m0.u[0], h2); fma2(acc[0][3], m0.u[0], h3);
        fma2(acc[1][0], m0.u[1], h0); fma2(acc[1][1], m0.u[1], h1);
        fma2(acc[1][2], m0.u[1], h2); fma2(acc[1][3], m0.u[1], h3);
        fma2(acc[2][0], m1.u[0], h0); fma2(acc[2][1], m1.u[0], h1);
        fma2(acc[2][2], m1.u[0], h2); fma2(acc[2][3], m1.u[0], h3);
        fma2(acc[3][0], m1.u[1], h0); fma2(acc[3][1], m1.u[1], h1);
        fma2(acc[3][2], m1.u[1], h2); fma2(acc[3][3], m1.u[1], h3);
    }

    // epilogue: add z + c1, relu → vf
    F2 vf[4][4];
    #pragma unroll
    for (int rp = 0; rp < 4; rp++) {
        int r0 = rg * 8 + 2 * rp;
        float cc0 = c1s[r0], cc1 = c1s[r0 + 1];
        #pragma unroll
        for (int q = 0; q < 4; q++) {
            float za, zb;
            if      (rp == 0) { za = zv0[q].x; zb = zv0[q].y; }
            else if (rp == 1) { za = zv0[q].z; zb = zv0[q].w; }
            else if (rp == 2) { za = zv1[q].x; zb = zv1[q].y; }
            else              { za = zv1[q].z; zb = zv1[q].w; }
            F2 t; t.u = acc[rp][q];
            vf[rp][q].f.x = fmaxf(t.f.x + za + cc0, 0.f);
            vf[rp][q].f.y = fmaxf(t.f.y + zb + cc1, 0.f);
        }
    }
    __syncthreads();   // all threads done reading H
    #pragma unroll
    for (int rp = 0; rp < 4; rp++) {
        int r0 = rg * 8 + 2 * rp;
        #pragma unroll
        for (int q = 0; q < 4; q++) {
            Hs[(r0    ) * 128 + col0 + q] = vf[rp][q].f.x;
            Hs[(r0 + 1) * 128 + col0 + q] = vf[rp][q].f.y;
        }
    }
    __syncthreads();

    // ---- stage 3: A = relu(A2 @ V + c2); partial max over k ----
    #pragma unroll
    for (int rp = 0; rp < 4; rp++)
        #pragma unroll
        for (int q = 0; q < 4; q++) acc[rp][q] = 0;

    #pragma unroll 8
    for (int c = 0; c < NC; c++) {
        const uint4* arow = (const uint4*)(A2p + c * 32 + rg * 4);
        U4 m0; m0.v = arow[0];
        U4 m1; m1.v = arow[1];
        float4 hv = *(const float4*)(Hs + c * 128 + col0);
        u64 h0 = dup2(hv.x), h1 = dup2(hv.y), h2 = dup2(hv.z), h3 = dup2(hv.w);
        fma2(acc[0][0], m0.u[0], h0); fma2(acc[0][1], m0.u[0], h1);
        fma2(acc[0][2], m0.u[0], h2); fma2(acc[0][3], m0.u[0], h3);
        fma2(acc[1][0], m0.u[1], h0); fma2(acc[1][1], m0.u[1], h1);
        fma2(acc[1][2], m0.u[1], h2); fma2(acc[1][3], m0.u[1], h3);
        fma2(acc[2][0], m1.u[0], h0); fma2(acc[2][1], m1.u[0], h1);
        fma2(acc[2][2], m1.u[0], h2); fma2(acc[2][3], m1.u[0], h3);
        fma2(acc[3][0], m1.u[1], h0); fma2(acc[3][1], m1.u[1], h1);
        fma2(acc[3][2], m1.u[1], h2); fma2(acc[3][3], m1.u[1], h3);
    }
    // epilogue: relu(+c2), max over own 4 cols, write partials (ys overlays Mp)
    #pragma unroll
    for (int rp = 0; rp < 4; rp++) {
        int r0 = rg * 8 + 2 * rp;
        float cc0 = c2s[r0], cc1 = c2s[r0 + 1];
        float pm0 = 0.f, pm1 = 0.f;   // relu output >= 0
        #pragma unroll
        for (int q = 0; q < 4; q++) {
            F2 t; t.u = acc[rp][q];
            pm0 = fmaxf(pm0, t.f.x + cc0);
            pm1 = fmaxf(pm1, t.f.y + cc1);
        }
        ys[(r0    ) * 32 + cg] = fmaxf(pm0, 0.f);
        ys[(r0 + 1) * 32 + cg] = fmaxf(pm1, 0.f);
    }
    __syncthreads();

    // reduce 4 partials -> yr[r][t]
    for (int e = tid; e < NC * TPB; e += 256) {
        int r = e >> 3, t = e & 7;
        const float* s = ys + r * 32 + t * 4;
        yr[r * 8 + t] = fmaxf(fmaxf(s[0], s[1]), fmaxf(s[2], s[3]));
    }
    __syncthreads();

    // ---- stage 4: out = D @ y + cd + x_in ----
    {
        int op = tid >> 3;          // row pair 0..31
        int t  = tid & 7;           // point
        const u64* Dg = dDcp[layer];
        u64 a0 = 0, a1 = 0;
        #pragma unroll 8
        for (int r = 0; r < NC; r += 2) {
            u64 d0 = __ldg(Dg + (r    ) * 32 + op);
            u64 d1 = __ldg(Dg + (r + 1) * 32 + op);
            fma2(a0, d0, dup2(yr[(r    ) * 8 + t]));
            fma2(a1, d1, dup2(yr[(r + 1) * 8 + t]));
        }
        F2 fa; fa.u = a0;
        F2 fb; fb.u = a1;
        int n = n0 + t;
        int r0 = 2 * op;
        const float* xi = x_in  + ((size_t)b * NC) * NPTS + n;
        float*       xo = x_out + ((size_t)b * NC) * NPTS + n;
        xo[(size_t)(r0    ) * NPTS] = fa.f.x + fb.f.x + dCd[layer][r0]     + xi[(size_t)(r0    ) * NPTS];
        xo[(size_t)(r0 + 1) * NPTS] = fa.f.y + fb.f.y + dCd[layer][r0 + 1] + xi[(size_t)(r0 + 1) * NPTS];
    }
}

// ---------------- launch ------------------------------------------------
extern "C" void kernel_launch(void* const* d_in, const int* in_sizes, int n_in,
                              void* d_out, int out_size)
{
    const float* p   = (const float*)d_in[0];
    const float* x   = (const float*)d_in[1];
    const int*   idx = (const int*)d_in[2];

    cudaFuncSetAttribute(main_kernel, cudaFuncAttributeMaxDynamicSharedMemorySize, SMEM_BYTES);

    prep_kernel<<<2, 64>>>(
        (const float*)d_in[3],  (const float*)d_in[4],  (const float*)d_in[5],  (const float*)d_in[6],
        (const float*)d_in[7],  (const float*)d_in[8],  (const float*)d_in[9],  (const float*)d_in[10],
        (const float*)d_in[11], (const float*)d_in[12], (const float*)d_in[13], (const float*)d_in[14],
        (const float*)d_in[15], (const float*)d_in[16], (const float*)d_in[17], (const float*)d_in[18],
        (const float*)d_in[19], (const float*)d_in[20], (const float*)d_in[21], (const float*)d_in[22]);

    float* out_p = (float*)d_out;
    float* out_x = (float*)d_out + NB * 3 * NPTS;

    cudaMemcpyAsync(out_p, p, (size_t)NB * 3 * NPTS * sizeof(float),
                    cudaMemcpyDeviceToDevice);

    dim3 zgrid(NPTS / 64, NB);
    int mblocks = NB * (NPTS / TPB);
    z_kernel<<<zgrid, 256>>>(x, 0);
    main_kernel<<<mblocks, 256, SMEM_BYTES>>>(p, x, idx, out_x, 0);
    z_kernel<<<zgrid, 256>>>(x, 1);
    main_kernel<<<mblocks, 256, SMEM_BYTES>>>(p, x, idx, out_x, 1);
}